// round 1
// baseline (speedup 1.0000x reference)
#include <cuda_runtime.h>
#include <math.h>

#define B_TOK 16384
#define D_DIM 2048
#define E_NUM 64
#define R_DIM 128
#define NASSIGN (2 * B_TOK)
#define CAP 640

// ---------------- scratch (static __device__ globals; no allocations) ----------------
__device__ float g_enc[(size_t)B_TOK * D_DIM];          // 134 MB
__device__ float g_logits[(size_t)B_TOK * E_NUM];       // 4 MB
__device__ int   g_eid[NASSIGN];
__device__ float g_w[NASSIGN];                          // weight if valid else 0
__device__ int   g_rows[E_NUM * CAP];                   // assignment ids per expert
__device__ int   g_cnt[E_NUM];
__device__ float g_h[(size_t)E_NUM * CAP * R_DIM];      // 21 MB
__device__ float g_dbuf[(size_t)NASSIGN * D_DIM];       // 268 MB

// =====================================================================
// Stage 1: enc = x @ We^T + be   (M=16384, N=2048, K=2048, NT, fp32)
// 128x128 block tile, BK=8, 256 threads, 8x8 per-thread microtile
// =====================================================================
__global__ void __launch_bounds__(256) k_gemm_enc(const float* __restrict__ A,
                                                  const float* __restrict__ W,
                                                  const float* __restrict__ bias) {
    __shared__ float As[8][128];
    __shared__ float Bs[8][128];
    const int tid = threadIdx.x;
    const int m0 = blockIdx.y * 128;
    const int n0 = blockIdx.x * 128;
    const int ty = tid >> 4, tx = tid & 15;
    const int lr = tid >> 1;
    const int lk = (tid & 1) * 4;
    const float* aptr = A + (size_t)(m0 + lr) * D_DIM + lk;
    const float* bptr = W + (size_t)(n0 + lr) * D_DIM + lk;

    float acc[8][8];
#pragma unroll
    for (int i = 0; i < 8; i++)
#pragma unroll
        for (int j = 0; j < 8; j++) acc[i][j] = 0.0f;

    for (int k0 = 0; k0 < D_DIM; k0 += 8) {
        float4 av = *(const float4*)(aptr + k0);
        float4 bv = *(const float4*)(bptr + k0);
        __syncthreads();
        As[lk + 0][lr] = av.x; As[lk + 1][lr] = av.y;
        As[lk + 2][lr] = av.z; As[lk + 3][lr] = av.w;
        Bs[lk + 0][lr] = bv.x; Bs[lk + 1][lr] = bv.y;
        Bs[lk + 2][lr] = bv.z; Bs[lk + 3][lr] = bv.w;
        __syncthreads();
#pragma unroll
        for (int kk = 0; kk < 8; kk++) {
            float4 a0 = *(const float4*)&As[kk][ty * 8];
            float4 a1 = *(const float4*)&As[kk][ty * 8 + 4];
            float4 b0 = *(const float4*)&Bs[kk][tx * 8];
            float4 b1 = *(const float4*)&Bs[kk][tx * 8 + 4];
            float a[8] = {a0.x, a0.y, a0.z, a0.w, a1.x, a1.y, a1.z, a1.w};
            float b[8] = {b0.x, b0.y, b0.z, b0.w, b1.x, b1.y, b1.z, b1.w};
#pragma unroll
            for (int i = 0; i < 8; i++)
#pragma unroll
                for (int j = 0; j < 8; j++) acc[i][j] += a[i] * b[j];
        }
    }

    const int row = m0 + ty * 8;
    const int col = n0 + tx * 8;
    float bb[8];
#pragma unroll
    for (int j = 0; j < 8; j++) bb[j] = bias[col + j];
#pragma unroll
    for (int i = 0; i < 8; i++) {
        float* cp = g_enc + (size_t)(row + i) * D_DIM + col;
#pragma unroll
        for (int j = 0; j < 8; j++) cp[j] = acc[i][j] + bb[j];
    }
}

// =====================================================================
// Stage 2: logits = enc @ Wg^T  (M=16384, N=64, K=2048, fp32)
// 128x64 block tile, BK=8, 256 threads, 8x4 per-thread
// =====================================================================
__global__ void __launch_bounds__(256) k_gemm_logits(const float* __restrict__ Wg) {
    __shared__ float As[8][128];
    __shared__ float Bs[8][64];
    const int tid = threadIdx.x;
    const int m0 = blockIdx.y * 128;
    const int ty = tid >> 4, tx = tid & 15;
    const int lr = tid >> 1;
    const int lk = (tid & 1) * 4;
    const float* aptr = g_enc + (size_t)(m0 + lr) * D_DIM + lk;
    const float* bptr = Wg + (size_t)(tid >> 1) * D_DIM + lk;  // valid when tid<128

    float acc[8][4];
#pragma unroll
    for (int i = 0; i < 8; i++)
#pragma unroll
        for (int j = 0; j < 4; j++) acc[i][j] = 0.0f;

    for (int k0 = 0; k0 < D_DIM; k0 += 8) {
        float4 av = *(const float4*)(aptr + k0);
        float4 bv = make_float4(0.f, 0.f, 0.f, 0.f);
        if (tid < 128) bv = *(const float4*)(bptr + k0);
        __syncthreads();
        As[lk + 0][lr] = av.x; As[lk + 1][lr] = av.y;
        As[lk + 2][lr] = av.z; As[lk + 3][lr] = av.w;
        if (tid < 128) {
            Bs[lk + 0][lr] = bv.x; Bs[lk + 1][lr] = bv.y;
            Bs[lk + 2][lr] = bv.z; Bs[lk + 3][lr] = bv.w;
        }
        __syncthreads();
#pragma unroll
        for (int kk = 0; kk < 8; kk++) {
            float4 a0 = *(const float4*)&As[kk][ty * 8];
            float4 a1 = *(const float4*)&As[kk][ty * 8 + 4];
            float4 b0 = *(const float4*)&Bs[kk][tx * 4];
            float a[8] = {a0.x, a0.y, a0.z, a0.w, a1.x, a1.y, a1.z, a1.w};
            float b[4] = {b0.x, b0.y, b0.z, b0.w};
#pragma unroll
            for (int i = 0; i < 8; i++)
#pragma unroll
                for (int j = 0; j < 4; j++) acc[i][j] += a[i] * b[j];
        }
    }
#pragma unroll
    for (int i = 0; i < 8; i++)
#pragma unroll
        for (int j = 0; j < 4; j++)
            g_logits[(size_t)(m0 + ty * 8 + i) * E_NUM + tx * 4 + j] = acc[i][j];
}

// =====================================================================
// Stage 3: per-token top-2 (jax tie semantics: strict >, earliest index)
// + masked softmax with +1e-12 eps
// =====================================================================
__global__ void __launch_bounds__(256) k_route() {
    const int t = blockIdx.x * blockDim.x + threadIdx.x;
    if (t >= B_TOK) return;
    const float* lg = g_logits + (size_t)t * E_NUM;
    float v0 = -INFINITY; int i0 = 0;
#pragma unroll 8
    for (int e = 0; e < E_NUM; e++) {
        float v = lg[e];
        if (v > v0) { v0 = v; i0 = e; }
    }
    float v1 = -INFINITY; int i1 = 0;
#pragma unroll 8
    for (int e = 0; e < E_NUM; e++) {
        if (e == i0) continue;
        float v = lg[e];
        if (v > v1) { v1 = v; i1 = e; }
    }
    // softmax over {v0, v1}, m = v0 (max)
    float e1 = expf(v1 - v0);
    float s = 1.0f + e1 + 1e-12f;
    float w0 = 1.0f / s;
    float w1 = e1 / s;
    g_eid[2 * t]     = i0;
    g_eid[2 * t + 1] = i1;
    g_w[2 * t]       = (w0 > 1e-12f) ? w0 : 0.0f;
    g_w[2 * t + 1]   = (w1 > 1e-12f) ? w1 : 0.0f;
}

// =====================================================================
// Stage 4: deterministic capacity scan (exact reference drop order).
// One block per expert scans all 32768 assignments in flattened order.
// =====================================================================
__global__ void __launch_bounds__(256) k_capacity() {
    const int e = blockIdx.x;
    const int tid = threadIdx.x;
    const int lane = tid & 31;
    const int wrp = tid >> 5;
    __shared__ int warp_cnt[8];
    int base = 0;
    for (int n0 = 0; n0 < NASSIGN; n0 += 256) {
        const int n = n0 + tid;
        const bool flag = (g_eid[n] == e) && (g_w[n] > 0.0f);
        unsigned m = __ballot_sync(0xffffffffu, flag);
        if (lane == 0) warp_cnt[wrp] = __popc(m);
        __syncthreads();
        int off = 0, tot = 0;
#pragma unroll
        for (int i = 0; i < 8; i++) {
            int c = warp_cnt[i];
            if (i < wrp) off += c;
            tot += c;
        }
        if (flag) {
            int pos = base + off + __popc(m & ((1u << lane) - 1u));
            if (pos < CAP) g_rows[e * CAP + pos] = n;
            else           g_w[n] = 0.0f;  // overflow: dropped exactly like reference
        }
        base += tot;
        __syncthreads();
    }
    if (tid == 0) g_cnt[e] = (base < CAP) ? base : CAP;
}

// =====================================================================
// Stage 5: H = silu(X_gathered @ U_e^T)   (M<=640 per expert, N=128, K=2048)
// 64x128 tile, BK=8, 256 threads, 4x8 per-thread
// =====================================================================
__device__ __forceinline__ float silu_f(float v) {
    return v / (1.0f + expf(-v));
}

__global__ void __launch_bounds__(256) k_gemm_expert1(const float* __restrict__ U) {
    const int e = blockIdx.y;
    const int cnt = g_cnt[e];
    const int m0 = blockIdx.x * 64;
    if (m0 >= cnt) return;
    __shared__ float As[8][64];
    __shared__ float Bs[8][128];
    const int tid = threadIdx.x;
    const int ty = tid >> 4, tx = tid & 15;
    const int lr = tid >> 1;
    const int lk = (tid & 1) * 4;

    int atok = -1;
    if (tid < 128) {
        if (m0 + lr < cnt) atok = g_rows[e * CAP + m0 + lr] >> 1;  // token id
    }
    const float* aptr = (atok >= 0) ? (g_enc + (size_t)atok * D_DIM + lk) : g_enc;
    const float* bptr = U + ((size_t)e * R_DIM + lr) * D_DIM + lk;

    float acc[4][8];
#pragma unroll
    for (int i = 0; i < 4; i++)
#pragma unroll
        for (int j = 0; j < 8; j++) acc[i][j] = 0.0f;

    for (int k0 = 0; k0 < D_DIM; k0 += 8) {
        float4 av = make_float4(0.f, 0.f, 0.f, 0.f);
        if (atok >= 0) av = *(const float4*)(aptr + k0);
        float4 bv = *(const float4*)(bptr + k0);
        __syncthreads();
        if (tid < 128) {
            As[lk + 0][lr] = av.x; As[lk + 1][lr] = av.y;
            As[lk + 2][lr] = av.z; As[lk + 3][lr] = av.w;
        }
        Bs[lk + 0][lr] = bv.x; Bs[lk + 1][lr] = bv.y;
        Bs[lk + 2][lr] = bv.z; Bs[lk + 3][lr] = bv.w;
        __syncthreads();
#pragma unroll
        for (int kk = 0; kk < 8; kk++) {
            float4 a0 = *(const float4*)&As[kk][ty * 4];
            float4 b0 = *(const float4*)&Bs[kk][tx * 8];
            float4 b1 = *(const float4*)&Bs[kk][tx * 8 + 4];
            float a[4] = {a0.x, a0.y, a0.z, a0.w};
            float b[8] = {b0.x, b0.y, b0.z, b0.w, b1.x, b1.y, b1.z, b1.w};
#pragma unroll
            for (int i = 0; i < 4; i++)
#pragma unroll
                for (int j = 0; j < 8; j++) acc[i][j] += a[i] * b[j];
        }
    }
#pragma unroll
    for (int i = 0; i < 4; i++) {
        int m = m0 + ty * 4 + i;
        if (m < cnt) {
            float* hp = g_h + ((size_t)e * CAP + m) * R_DIM + tx * 8;
#pragma unroll
            for (int j = 0; j < 8; j++) hp[j] = silu_f(acc[i][j]);
        }
    }
}

// =====================================================================
// Stage 6: dbuf[n] = (w * gamma_e) * (H @ V_e^T)  (M<=640, N=2048, K=128)
// =====================================================================
__global__ void __launch_bounds__(256) k_gemm_expert2(const float* __restrict__ V,
                                                      const float* __restrict__ gamma) {
    const int e = blockIdx.z;
    const int cnt = g_cnt[e];
    const int m0 = blockIdx.y * 64;
    if (m0 >= cnt) return;
    const int n0 = blockIdx.x * 128;
    __shared__ float As[8][64];
    __shared__ float Bs[8][128];
    const int tid = threadIdx.x;
    const int ty = tid >> 4, tx = tid & 15;
    const int lr = tid >> 1;
    const int lk = (tid & 1) * 4;

    const bool arow_ok = (tid < 128) && (m0 + lr < cnt);
    const float* aptr = g_h + ((size_t)e * CAP + m0 + lr) * R_DIM + lk;
    const float* bptr = V + ((size_t)e * D_DIM + n0 + lr) * R_DIM + lk;

    float acc[4][8];
#pragma unroll
    for (int i = 0; i < 4; i++)
#pragma unroll
        for (int j = 0; j < 8; j++) acc[i][j] = 0.0f;

    for (int k0 = 0; k0 < R_DIM; k0 += 8) {
        float4 av = make_float4(0.f, 0.f, 0.f, 0.f);
        if (arow_ok) av = *(const float4*)(aptr + k0);
        float4 bv = *(const float4*)(bptr + k0);
        __syncthreads();
        if (tid < 128) {
            As[lk + 0][lr] = av.x; As[lk + 1][lr] = av.y;
            As[lk + 2][lr] = av.z; As[lk + 3][lr] = av.w;
        }
        Bs[lk + 0][lr] = bv.x; Bs[lk + 1][lr] = bv.y;
        Bs[lk + 2][lr] = bv.z; Bs[lk + 3][lr] = bv.w;
        __syncthreads();
#pragma unroll
        for (int kk = 0; kk < 8; kk++) {
            float4 a0 = *(const float4*)&As[kk][ty * 4];
            float4 b0 = *(const float4*)&Bs[kk][tx * 8];
            float4 b1 = *(const float4*)&Bs[kk][tx * 8 + 4];
            float a[4] = {a0.x, a0.y, a0.z, a0.w};
            float b[8] = {b0.x, b0.y, b0.z, b0.w, b1.x, b1.y, b1.z, b1.w};
#pragma unroll
            for (int i = 0; i < 4; i++)
#pragma unroll
                for (int j = 0; j < 8; j++) acc[i][j] += a[i] * b[j];
        }
    }
    const float gm = gamma[e];
#pragma unroll
    for (int i = 0; i < 4; i++) {
        int m = m0 + ty * 4 + i;
        if (m < cnt) {
            int n = g_rows[e * CAP + m];
            float scale = g_w[n] * gm;
            float* dp = g_dbuf + (size_t)n * D_DIM + n0 + tx * 8;
#pragma unroll
            for (int j = 0; j < 8; j++) dp[j] = acc[i][j] * scale;
        }
    }
}

// =====================================================================
// Stage 7: y[t] = enc[t] + dbuf[2t] (if valid) + dbuf[2t+1] (if valid)
// =====================================================================
__global__ void __launch_bounds__(512) k_combine(float* __restrict__ y) {
    const int t = blockIdx.x;
    const int d4 = threadIdx.x;  // 0..511 (float4 units, D/4 = 512)
    const float4* enc4 = (const float4*)g_enc;
    const float4* db4 = (const float4*)g_dbuf;
    float4 r = enc4[(size_t)t * 512 + d4];
    const float w0 = g_w[2 * t];
    const float w1 = g_w[2 * t + 1];
    if (w0 > 0.0f) {
        float4 a = db4[(size_t)(2 * t) * 512 + d4];
        r.x += a.x; r.y += a.y; r.z += a.z; r.w += a.w;
    }
    if (w1 > 0.0f) {
        float4 a = db4[(size_t)(2 * t + 1) * 512 + d4];
        r.x += a.x; r.y += a.y; r.z += a.z; r.w += a.w;
    }
    ((float4*)y)[(size_t)t * 512 + d4] = r;
}

// =====================================================================
extern "C" void kernel_launch(void* const* d_in, const int* in_sizes, int n_in,
                              void* d_out, int out_size) {
    const float* x     = (const float*)d_in[0];
    const float* We    = (const float*)d_in[1];
    const float* be    = (const float*)d_in[2];
    const float* Wg    = (const float*)d_in[3];
    const float* U     = (const float*)d_in[4];
    const float* V     = (const float*)d_in[5];
    const float* gamma = (const float*)d_in[6];
    float* y = (float*)d_out;

    dim3 gEnc(D_DIM / 128, B_TOK / 128);            // 16 x 128
    k_gemm_enc<<<gEnc, 256>>>(x, We, be);

    dim3 gLog(1, B_TOK / 128);                      // 1 x 128
    k_gemm_logits<<<gLog, 256>>>(Wg);

    k_route<<<B_TOK / 256, 256>>>();

    k_capacity<<<E_NUM, 256>>>();

    dim3 gE1(CAP / 64, E_NUM);                      // 10 x 64
    k_gemm_expert1<<<gE1, 256>>>(U);

    dim3 gE2(D_DIM / 128, CAP / 64, E_NUM);         // 16 x 10 x 64
    k_gemm_expert2<<<gE2, 256>>>(V, gamma);

    k_combine<<<B_TOK, 512>>>(y);
}